// round 1
// baseline (speedup 1.0000x reference)
#include <cuda_runtime.h>

typedef unsigned long long ull;

#define CHUNKSZ 512
#define BB 4
#define SS 4096
#define HH 1024
#define FF 4096
#define NCHUNK 8
#define MROWS (BB*CHUNKSZ)          /* 2048 */
#define NOUT (BB*SS*HH)             /* 16777216 */

// Scratch (device globals -- no allocations allowed)
__device__ float g_u0[(size_t)MROWS * FF];   // u0, then v = silu(D*u0)*u2 in place
__device__ float g_u2[(size_t)MROWS * FF];
__device__ float g_partial[128];
__device__ float g_D;
__device__ float g_total;

// ---- packed f32x2 helpers (full-rate fp32 on Blackwell) ----
__device__ __forceinline__ ull fma2(ull a, ull b, ull c) {
    ull d; asm("fma.rn.f32x2 %0, %1, %2, %3;" : "=l"(d) : "l"(a), "l"(b), "l"(c)); return d;
}
__device__ __forceinline__ ull dup2(float a) {
    ull d; asm("mov.b64 %0, {%1, %1};" : "=l"(d) : "f"(a)); return d;
}
__device__ __forceinline__ float2 unpk(ull v) {
    float2 r; asm("mov.b64 {%0, %1}, %2;" : "=f"(r.x), "=f"(r.y) : "l"(v)); return r;
}

__global__ void init_kernel() { g_D = 1.0f; g_total = 0.0f; }

// v = silu(D * u0) * u2, in place into g_u0
__global__ void silu_mul_kernel() {
    float D = g_D;
    int i = (blockIdx.x * blockDim.x + threadIdx.x) * 4;
    float4 a = *(const float4*)&g_u0[i];
    float4 b = *(const float4*)&g_u2[i];
    float4 v; float z;
    z = D * a.x; v.x = (z / (1.0f + __expf(-z))) * b.x;
    z = D * a.y; v.y = (z / (1.0f + __expf(-z))) * b.y;
    z = D * a.z; v.z = (z / (1.0f + __expf(-z))) * b.z;
    z = D * a.w; v.w = (z / (1.0f + __expf(-z))) * b.w;
    *(float4*)&g_u0[i] = v;
}

__global__ void reduce_update_kernel(float* __restrict__ outp, int chunk) {
    __shared__ float red[128];
    int t = threadIdx.x;
    red[t] = g_partial[t];
    __syncthreads();
    for (int s = 64; s > 0; s >>= 1) {
        if (t < s) red[t] += red[t + s];
        __syncthreads();
    }
    if (t == 0) {
        float loss = red[0] * (1.0f / (float)(BB * CHUNKSZ * HH));
        float tot = g_total + loss;
        g_total = tot;
        g_D = g_D * (1.0f - 0.001f * loss);
        if (chunk == NCHUNK - 1) outp[NOUT] = tot * (1.0f / (float)NCHUNK);
    }
}

// 128x128x16 tiled GEMM, 256 threads, 8x8/thread via f32x2.
// G2=false: u = x_chunk @ W (W = w0 or w2 by blockIdx.z), K=1024, N=4096
// G2=true : out = D^2 * (v @ w1), K=4096, N=1024, fused (out-x)^2 partial sums
template<int KTOT, int NTOT, int LDA, bool G2>
__global__ __launch_bounds__(256, 2)
void gemm_kernel(const float* __restrict__ xin,
                 const float* __restrict__ B0,
                 const float* __restrict__ B1,
                 float* __restrict__ outp,
                 int chunk)
{
    __shared__ float As[2][16][128];
    __shared__ float Bs[2][16][128];
    __shared__ float red[256];

    const int tid = threadIdx.x;
    const int m0 = blockIdx.y * 128;
    const int n0 = blockIdx.x * 128;

    const float* Asrc = G2 ? (const float*)g_u0 : xin;
    const float* Bsrc = (!G2 && blockIdx.z == 1) ? B1 : B0;

    // A loaders: 2 float4 per thread, rows r0 and r0+64, k-quad c4
    const int r0 = tid >> 2, c4 = tid & 3;
    const int mA0 = m0 + r0, mA1 = m0 + r0 + 64;
    int ga0, ga1;
    if (G2) { ga0 = mA0; ga1 = mA1; }
    else {
        ga0 = ((mA0 >> 9) << 12) + chunk * CHUNKSZ + (mA0 & 511);
        ga1 = ((mA1 >> 9) << 12) + chunk * CHUNKSZ + (mA1 & 511);
    }
    const float* pa0 = Asrc + (size_t)ga0 * LDA + c4 * 4;
    const float* pa1 = Asrc + (size_t)ga1 * LDA + c4 * 4;
    // B loaders: 2 float4 per thread, k-rows kr and kr+8
    const int kr = tid >> 5, nc = tid & 31;
    const float* pb0 = Bsrc + (size_t)kr * NTOT + n0 + nc * 4;
    const float* pb1 = pb0 + (size_t)8 * NTOT;

    ull acc[8][4];
    #pragma unroll
    for (int i = 0; i < 8; i++)
        #pragma unroll
        for (int j = 0; j < 4; j++) acc[i][j] = 0ull;

    // prefetch tile 0
    float4 ra0 = *(const float4*)pa0;
    float4 ra1 = *(const float4*)pa1;
    float4 rb0 = *(const float4*)pb0;
    float4 rb1 = *(const float4*)pb1;
    pa0 += 16; pa1 += 16;
    pb0 += (size_t)16 * NTOT; pb1 += (size_t)16 * NTOT;

    // stage tile 0 (A transposed into As[k][m])
    As[0][c4*4+0][r0] = ra0.x; As[0][c4*4+1][r0] = ra0.y;
    As[0][c4*4+2][r0] = ra0.z; As[0][c4*4+3][r0] = ra0.w;
    As[0][c4*4+0][r0+64] = ra1.x; As[0][c4*4+1][r0+64] = ra1.y;
    As[0][c4*4+2][r0+64] = ra1.z; As[0][c4*4+3][r0+64] = ra1.w;
    *(float4*)&Bs[0][kr][nc*4]   = rb0;
    *(float4*)&Bs[0][kr+8][nc*4] = rb1;
    __syncthreads();

    const int tx = tid & 15, ty = tid >> 4;
    const int KT = KTOT / 16;

    for (int kt = 0; kt < KT; ++kt) {
        const int buf = kt & 1;
        if (kt + 1 < KT) {
            ra0 = *(const float4*)pa0;
            ra1 = *(const float4*)pa1;
            rb0 = *(const float4*)pb0;
            rb1 = *(const float4*)pb1;
            pa0 += 16; pa1 += 16;
            pb0 += (size_t)16 * NTOT; pb1 += (size_t)16 * NTOT;
        }
        #pragma unroll
        for (int k = 0; k < 16; ++k) {
            const float* ap = &As[buf][k][ty * 8];
            float4 av0 = *(const float4*)ap;
            float4 av1 = *(const float4*)(ap + 4);
            const ull* bp = (const ull*)&Bs[buf][k][tx * 8];
            ull bv0 = bp[0], bv1 = bp[1], bv2 = bp[2], bv3 = bp[3];
            float a[8] = {av0.x, av0.y, av0.z, av0.w, av1.x, av1.y, av1.z, av1.w};
            #pragma unroll
            for (int i = 0; i < 8; ++i) {
                ull ai = dup2(a[i]);
                acc[i][0] = fma2(ai, bv0, acc[i][0]);
                acc[i][1] = fma2(ai, bv1, acc[i][1]);
                acc[i][2] = fma2(ai, bv2, acc[i][2]);
                acc[i][3] = fma2(ai, bv3, acc[i][3]);
            }
        }
        if (kt + 1 < KT) {
            const int nb = buf ^ 1;
            As[nb][c4*4+0][r0] = ra0.x; As[nb][c4*4+1][r0] = ra0.y;
            As[nb][c4*4+2][r0] = ra0.z; As[nb][c4*4+3][r0] = ra0.w;
            As[nb][c4*4+0][r0+64] = ra1.x; As[nb][c4*4+1][r0+64] = ra1.y;
            As[nb][c4*4+2][r0+64] = ra1.z; As[nb][c4*4+3][r0+64] = ra1.w;
            *(float4*)&Bs[nb][kr][nc*4]   = rb0;
            *(float4*)&Bs[nb][kr+8][nc*4] = rb1;
        }
        __syncthreads();
    }

    if (!G2) {
        float* Cp = (blockIdx.z == 0) ? g_u0 : g_u2;
        #pragma unroll
        for (int i = 0; i < 8; ++i) {
            const int m = m0 + ty * 8 + i;
            float* cp = Cp + (size_t)m * NTOT + n0 + tx * 8;
            float2 p0 = unpk(acc[i][0]), p1 = unpk(acc[i][1]);
            float2 p2 = unpk(acc[i][2]), p3 = unpk(acc[i][3]);
            *(float4*)cp       = make_float4(p0.x, p0.y, p1.x, p1.y);
            *(float4*)(cp + 4) = make_float4(p2.x, p2.y, p3.x, p3.y);
        }
    } else {
        const float Dv = g_D;
        const float D2 = Dv * Dv;
        float sq = 0.0f;
        #pragma unroll
        for (int i = 0; i < 8; ++i) {
            const int m = m0 + ty * 8 + i;
            const int grow = ((m >> 9) << 12) + chunk * CHUNKSZ + (m & 511);
            const float* xp = xin + (size_t)grow * HH + n0 + tx * 8;
            float* op = outp + (size_t)grow * HH + n0 + tx * 8;
            float4 x0 = *(const float4*)xp;
            float4 x1 = *(const float4*)(xp + 4);
            float2 p0 = unpk(acc[i][0]), p1 = unpk(acc[i][1]);
            float2 p2 = unpk(acc[i][2]), p3 = unpk(acc[i][3]);
            float4 o0 = make_float4(D2 * p0.x, D2 * p0.y, D2 * p1.x, D2 * p1.y);
            float4 o1 = make_float4(D2 * p2.x, D2 * p2.y, D2 * p3.x, D2 * p3.y);
            *(float4*)op       = o0;
            *(float4*)(op + 4) = o1;
            float d;
            d = o0.x - x0.x; sq += d * d;
            d = o0.y - x0.y; sq += d * d;
            d = o0.z - x0.z; sq += d * d;
            d = o0.w - x0.w; sq += d * d;
            d = o1.x - x1.x; sq += d * d;
            d = o1.y - x1.y; sq += d * d;
            d = o1.z - x1.z; sq += d * d;
            d = o1.w - x1.w; sq += d * d;
        }
        red[tid] = sq;
        __syncthreads();
        for (int s = 128; s > 0; s >>= 1) {
            if (tid < s) red[tid] += red[tid + s];
            __syncthreads();
        }
        if (tid == 0) g_partial[blockIdx.y * gridDim.x + blockIdx.x] = red[0];
    }
}

extern "C" void kernel_launch(void* const* d_in, const int* in_sizes, int n_in,
                              void* d_out, int out_size)
{
    const float* x  = (const float*)d_in[0];
    const float* w0 = (const float*)d_in[1];
    const float* w1 = (const float*)d_in[2];
    const float* w2 = (const float*)d_in[3];
    float* out = (float*)d_out;

    init_kernel<<<1, 1>>>();
    for (int c = 0; c < NCHUNK; ++c) {
        // u0 = xc @ w0, u2 = xc @ w2   (z selects weight)
        gemm_kernel<1024, 4096, 1024, false><<<dim3(32, 16, 2), 256>>>(x, w0, w2, nullptr, c);
        // v = silu(D*u0) * u2 (in place in g_u0)
        silu_mul_kernel<<<8192, 256>>>();
        // out_c = D^2 * (v @ w1), fused squared-error partials
        gemm_kernel<4096, 1024, 4096, true><<<dim3(8, 16, 1), 256>>>(x, w1, nullptr, out, c);
        // chunk loss -> decay D, accumulate total loss (writes d_out[NOUT] on last chunk)
        reduce_update_kernel<<<1, 128>>>(out, c);
    }
}

// round 3
// speedup vs baseline: 2.8134x; 2.8134x over previous
#include <cuda_runtime.h>
#include <cstdint>

typedef uint32_t u32;

#define CHUNKSZ 512
#define NCHUNK  8
#define HH      1024
#define FF      4096
#define MROWS   2048
#define NOUT    16777216

// ---- scratch (device globals; no allocations allowed) ----
__device__ float g_xr[(size_t)NOUT];          // tf32-rounded x (64MB)
__device__ float g_v [(size_t)MROWS * FF];    // v = silu(D*u0)*u2 (32MB)
__device__ float g_w0T[(size_t)FF * HH];      // w0^T [n=4096][k=1024], tf32-rounded
__device__ float g_w2T[(size_t)FF * HH];
__device__ float g_w1T[(size_t)HH * FF];      // w1^T [n=1024][k=4096]
__device__ float g_partial[128];
__device__ float g_D;
__device__ float g_total;

// =================== helpers ===================
__device__ __forceinline__ u32 smem_u32(const void* p) {
    u32 a; asm("{ .reg .u64 t; cvta.to.shared.u64 t, %1; cvt.u32.u64 %0, t; }" : "=r"(a) : "l"(p));
    return a;
}
__device__ __forceinline__ float to_tf32(float x) {
    u32 r; asm("cvt.rna.tf32.f32 %0, %1;" : "=r"(r) : "f"(x));
    return __uint_as_float(r);
}

#define CP16(dst, src) \
    asm volatile("cp.async.cg.shared.global [%0], [%1], 16;" :: "r"(dst), "l"(src) : "memory")
#define CPCOMMIT() asm volatile("cp.async.commit_group;" ::: "memory")
#define CPWAIT1()  asm volatile("cp.async.wait_group 1;" ::: "memory")

#define LDSM4(r, addr) \
    asm volatile("ldmatrix.sync.aligned.m8n8.x4.shared.b16 {%0,%1,%2,%3}, [%4];" \
        : "=r"((r)[0]), "=r"((r)[1]), "=r"((r)[2]), "=r"((r)[3]) : "r"(addr))

#define MMA8(d, a, b0_, b1_) \
    asm volatile("mma.sync.aligned.m16n8k8.row.col.f32.tf32.tf32.f32 " \
        "{%0,%1,%2,%3}, {%4,%5,%6,%7}, {%8,%9}, {%0,%1,%2,%3};" \
        : "+f"((d)[0]), "+f"((d)[1]), "+f"((d)[2]), "+f"((d)[3]) \
        : "r"((a)[0]), "r"((a)[1]), "r"((a)[2]), "r"((a)[3]), "r"(b0_), "r"(b1_))

// tile: 128 rows x 32 k-floats, row stride 36 floats (144B) -> conflict-free LDSM/STS
#define TILE_B   18432   /* 128*36*4 */
#define ROWSTR   144

// =================== small kernels ===================
__global__ void init_kernel() { g_D = 1.0f; g_total = 0.0f; }

__global__ void round_x_kernel(const float* __restrict__ x) {
    int i = (blockIdx.x * 256 + threadIdx.x) * 4;
    float4 v = *(const float4*)(x + i);
    v.x = to_tf32(v.x); v.y = to_tf32(v.y); v.z = to_tf32(v.z); v.w = to_tf32(v.w);
    *(float4*)(g_xr + i) = v;
}

// out[C][R] = tf32_round(in[R][C]); block (32,8), grid (C/32, R/32)
__global__ void transpose_w(const float* __restrict__ in, float* __restrict__ out, int R, int C) {
    __shared__ float t[32][33];
    int c0 = blockIdx.x * 32, r0 = blockIdx.y * 32;
    #pragma unroll
    for (int i = 0; i < 32; i += 8)
        t[threadIdx.y + i][threadIdx.x] = in[(size_t)(r0 + threadIdx.y + i) * C + c0 + threadIdx.x];
    __syncthreads();
    #pragma unroll
    for (int i = 0; i < 32; i += 8)
        out[(size_t)(c0 + threadIdx.y + i) * R + r0 + threadIdx.x] = to_tf32(t[threadIdx.x][threadIdx.y + i]);
}

__global__ void reduce_update_kernel(float* __restrict__ outp, int chunk) {
    __shared__ float red[128];
    int t = threadIdx.x;
    red[t] = g_partial[t];
    __syncthreads();
    for (int s = 64; s > 0; s >>= 1) {
        if (t < s) red[t] += red[t + s];
        __syncthreads();
    }
    if (t == 0) {
        float loss = red[0] * (1.0f / (float)(MROWS * HH));
        float tot = g_total + loss;
        g_total = tot;
        g_D = g_D * (1.0f - 0.001f * loss);
        if (chunk == NCHUNK - 1) outp[NOUT] = tot * (1.0f / (float)NCHUNK);
    }
}

// =================== GEMM1: u0/u2 (both weights) + fused SwiGLU -> g_v ===================
// CTA 128x128, K=1024. smem stage = [A | B(w0) | B(w2)] = 3*18432; 3 stages = 165888 B.
#define ST1_STAGE (3 * TILE_B)
#define ST1_BYTES (3 * ST1_STAGE)

__device__ __forceinline__ void g1_load(u32 base, int tid, int m0, int n0, int chunk, int kt) {
    #pragma unroll
    for (int i = 0; i < 4; i++) {
        int idx = tid + i * 256;
        int row = idx >> 3, kq = idx & 7;
        int gm = m0 + row;
        int g = ((gm >> 9) << 12) + chunk * CHUNKSZ + (gm & 511);
        const float* src = g_xr + (size_t)g * HH + kt * 32 + kq * 4;
        CP16(base + (u32)(row * ROWSTR + kq * 16), src);
    }
    #pragma unroll
    for (int i = 0; i < 8; i++) {
        int idx = tid + i * 256;
        int w = idx >> 10, r2 = idx & 1023;
        int row = r2 >> 3, kq = r2 & 7;
        const float* src = (w ? g_w2T : g_w0T) + (size_t)(n0 + row) * HH + kt * 32 + kq * 4;
        CP16(base + (u32)(1 + w) * TILE_B + (u32)(row * ROWSTR + kq * 16), src);
    }
}

__global__ __launch_bounds__(256, 1)
void gemm1_tc(int chunk)
{
    extern __shared__ float smem[];
    const u32 sb = smem_u32(smem);
    const int tid = threadIdx.x, lane = tid & 31, wid = tid >> 5;
    const int wm = wid & 3, wn = wid >> 2;
    const int m0 = blockIdx.y * 128, n0 = blockIdx.x * 128;

    float acc0[2][8][4], acc2[2][8][4];
    #pragma unroll
    for (int a = 0; a < 2; a++)
        #pragma unroll
        for (int b = 0; b < 8; b++)
            #pragma unroll
            for (int c = 0; c < 4; c++) { acc0[a][b][c] = 0.f; acc2[a][b][c] = 0.f; }

    const u32 aoff = (u32)((wm * 32 + (lane & 15)) * ROWSTR) + ((lane >> 4) & 1) * 16;
    const u32 boff = (u32)((wn * 64 + (lane & 15)) * ROWSTR) + ((lane >> 4) & 1) * 16;

    g1_load(sb, tid, m0, n0, chunk, 0); CPCOMMIT();
    g1_load(sb + ST1_STAGE, tid, m0, n0, chunk, 1); CPCOMMIT();

    const int KT = HH / 32;  // 32
    for (int kt = 0; kt < KT; ++kt) {
        const u32 base = sb + (u32)(kt % 3) * ST1_STAGE;
        CPWAIT1();
        __syncthreads();
        if (kt + 2 < KT) g1_load(sb + (u32)((kt + 2) % 3) * ST1_STAGE, tid, m0, n0, chunk, kt + 2);
        CPCOMMIT();
        #pragma unroll
        for (int ks = 0; ks < 4; ++ks) {
            u32 A[2][4];
            LDSM4(A[0], base + aoff + 0 * 2304 + ks * 32);
            LDSM4(A[1], base + aoff + 1 * 2304 + ks * 32);
            #pragma unroll
            for (int tp = 0; tp < 4; ++tp) {
                u32 b[4], c[4];
                LDSM4(b, base + 1 * TILE_B + boff + tp * 2304 + ks * 32);
                LDSM4(c, base + 2 * TILE_B + boff + tp * 2304 + ks * 32);
                #pragma unroll
                for (int mt = 0; mt < 2; ++mt) {
                    MMA8(acc0[mt][2 * tp],     A[mt], b[0], b[2]);
                    MMA8(acc0[mt][2 * tp + 1], A[mt], b[1], b[3]);
                    MMA8(acc2[mt][2 * tp],     A[mt], c[0], c[2]);
                    MMA8(acc2[mt][2 * tp + 1], A[mt], c[1], c[3]);
                }
            }
        }
    }

    // fused SwiGLU epilogue -> g_v (tf32-rounded)
    const float D = g_D;
    const int gq = lane >> 2, tg = lane & 3;
    #pragma unroll
    for (int mt = 0; mt < 2; ++mt) {
        #pragma unroll
        for (int nt = 0; nt < 8; ++nt) {
            const int col = n0 + wn * 64 + nt * 8 + tg * 2;
            #pragma unroll
            for (int h = 0; h < 2; ++h) {
                const int row = m0 + wm * 32 + mt * 16 + gq + h * 8;
                float u0a = acc0[mt][nt][h * 2], u0b = acc0[mt][nt][h * 2 + 1];
                float u2a = acc2[mt][nt][h * 2], u2b = acc2[mt][nt][h * 2 + 1];
                float z, s;
                float2 vv;
                z = D * u0a; s = z / (1.0f + __expf(-z)); vv.x = to_tf32(s * u2a);
                z = D * u0b; s = z / (1.0f + __expf(-z)); vv.y = to_tf32(s * u2b);
                *(float2*)&g_v[(size_t)row * FF + col] = vv;
            }
        }
    }
}

// =================== GEMM2: out = D^2 * (v @ w1T) + fused loss partials ===================
// CTA 128x128, K=4096. smem stage = [A | B] = 2*18432; 3 stages = 110592 B.
#define ST2_STAGE (2 * TILE_B)
#define ST2_BYTES (3 * ST2_STAGE)

__device__ __forceinline__ void g2_load(u32 base, int tid, int m0, int n0, int kt) {
    #pragma unroll
    for (int i = 0; i < 4; i++) {
        int idx = tid + i * 256;
        int row = idx >> 3, kq = idx & 7;
        const float* src = g_v + (size_t)(m0 + row) * FF + kt * 32 + kq * 4;
        CP16(base + (u32)(row * ROWSTR + kq * 16), src);
    }
    #pragma unroll
    for (int i = 0; i < 4; i++) {
        int idx = tid + i * 256;
        int row = idx >> 3, kq = idx & 7;
        const float* src = g_w1T + (size_t)(n0 + row) * FF + kt * 32 + kq * 4;
        CP16(base + TILE_B + (u32)(row * ROWSTR + kq * 16), src);
    }
}

__global__ __launch_bounds__(256, 1)
void gemm2_tc(const float* __restrict__ x, float* __restrict__ outp, int chunk)
{
    extern __shared__ float smem[];
    const u32 sb = smem_u32(smem);
    const int tid = threadIdx.x, lane = tid & 31, wid = tid >> 5;
    const int wm = wid & 3, wn = wid >> 2;
    const int m0 = blockIdx.y * 128, n0 = blockIdx.x * 128;

    float acc[2][8][4];
    #pragma unroll
    for (int a = 0; a < 2; a++)
        #pragma unroll
        for (int b = 0; b < 8; b++)
            #pragma unroll
            for (int c = 0; c < 4; c++) acc[a][b][c] = 0.f;

    const u32 aoff = (u32)((wm * 32 + (lane & 15)) * ROWSTR) + ((lane >> 4) & 1) * 16;
    const u32 boff = (u32)((wn * 64 + (lane & 15)) * ROWSTR) + ((lane >> 4) & 1) * 16;

    g2_load(sb, tid, m0, n0, 0); CPCOMMIT();
    g2_load(sb + ST2_STAGE, tid, m0, n0, 1); CPCOMMIT();

    const int KT = FF / 32;  // 128
    for (int kt = 0; kt < KT; ++kt) {
        const u32 base = sb + (u32)(kt % 3) * ST2_STAGE;
        CPWAIT1();
        __syncthreads();
        if (kt + 2 < KT) g2_load(sb + (u32)((kt + 2) % 3) * ST2_STAGE, tid, m0, n0, kt + 2);
        CPCOMMIT();
        #pragma unroll
        for (int ks = 0; ks < 4; ++ks) {
            u32 A[2][4];
            LDSM4(A[0], base + aoff + 0 * 2304 + ks * 32);
            LDSM4(A[1], base + aoff + 1 * 2304 + ks * 32);
            #pragma unroll
            for (int tp = 0; tp < 4; ++tp) {
                u32 b[4];
                LDSM4(b, base + TILE_B + boff + tp * 2304 + ks * 32);
                #pragma unroll
                for (int mt = 0; mt < 2; ++mt) {
                    MMA8(acc[mt][2 * tp],     A[mt], b[0], b[2]);
                    MMA8(acc[mt][2 * tp + 1], A[mt], b[1], b[3]);
                }
            }
        }
    }

    // epilogue: out = D^2*acc, fused (out - x)^2 partial
    const float D = g_D, D2 = D * D;
    const int gq = lane >> 2, tg = lane & 3;
    float sq = 0.0f;
    #pragma unroll
    for (int mt = 0; mt < 2; ++mt) {
        #pragma unroll
        for (int nt = 0; nt < 8; ++nt) {
            const int col = n0 + wn * 64 + nt * 8 + tg * 2;
            #pragma unroll
            for (int h = 0; h < 2; ++h) {
                const int lm = m0 + wm * 32 + mt * 16 + gq + h * 8;
                const int g = ((lm >> 9) << 12) + chunk * CHUNKSZ + (lm & 511);
                float2 xv = *(const float2*)(x + (size_t)g * HH + col);
                float2 ov;
                ov.x = D2 * acc[mt][nt][h * 2];
                ov.y = D2 * acc[mt][nt][h * 2 + 1];
                *(float2*)(outp + (size_t)g * HH + col) = ov;
                float d0 = ov.x - xv.x, d1 = ov.y - xv.y;
                sq += d0 * d0 + d1 * d1;
            }
        }
    }
    // block reduce
    #pragma unroll
    for (int off = 16; off > 0; off >>= 1)
        sq += __shfl_xor_sync(0xFFFFFFFFu, sq, off);
    __syncthreads();               // smem stages no longer needed
    float* red = smem;
    if (lane == 0) red[wid] = sq;
    __syncthreads();
    if (tid == 0) {
        float s = 0.f;
        #pragma unroll
        for (int i = 0; i < 8; i++) s += red[i];
        g_partial[blockIdx.y * 8 + blockIdx.x] = s;
    }
}

// =================== host ===================
extern "C" void kernel_launch(void* const* d_in, const int* in_sizes, int n_in,
                              void* d_out, int out_size)
{
    const float* x  = (const float*)d_in[0];
    const float* w0 = (const float*)d_in[1];
    const float* w1 = (const float*)d_in[2];
    const float* w2 = (const float*)d_in[3];
    float* out = (float*)d_out;

    cudaFuncSetAttribute(gemm1_tc, cudaFuncAttributeMaxDynamicSharedMemorySize, ST1_BYTES);
    cudaFuncSetAttribute(gemm2_tc, cudaFuncAttributeMaxDynamicSharedMemorySize, ST2_BYTES);

    float *p0, *p1, *p2;
    cudaGetSymbolAddress((void**)&p0, g_w0T);
    cudaGetSymbolAddress((void**)&p1, g_w1T);
    cudaGetSymbolAddress((void**)&p2, g_w2T);

    init_kernel<<<1, 1>>>();
    round_x_kernel<<<NOUT / 1024, 256>>>(x);
    transpose_w<<<dim3(FF / 32, HH / 32), dim3(32, 8)>>>(w0, p0, HH, FF);
    transpose_w<<<dim3(FF / 32, HH / 32), dim3(32, 8)>>>(w2, p2, HH, FF);
    transpose_w<<<dim3(HH / 32, FF / 32), dim3(32, 8)>>>(w1, p1, FF, HH);

    for (int c = 0; c < NCHUNK; ++c) {
        gemm1_tc<<<dim3(32, 16), 256, ST1_BYTES>>>(c);
        gemm2_tc<<<dim3(8, 16), 256, ST2_BYTES>>>(x, out, c);
        reduce_update_kernel<<<1, 128>>>(out, c);
    }
}

// round 6
// speedup vs baseline: 5.2098x; 1.8517x over previous
#include <cuda_runtime.h>
#include <cuda_fp16.h>
#include <cstdint>

typedef uint32_t u32;

#define CHUNKSZ 512
#define NCHUNK  8
#define HH      1024
#define FF      4096
#define MROWS   2048
#define NOUT    16777216

// ---- scratch (device globals; no allocations allowed) ----
__device__ __half g_xh[(size_t)NOUT];          // fp16 x (32MB)
__device__ __half g_vh[(size_t)MROWS * FF];    // v = silu(D*u0)*u2 (16MB)
__device__ __half g_w0T[(size_t)FF * HH];      // w0^T [n=4096][k=1024]
__device__ __half g_w2T[(size_t)FF * HH];
__device__ __half g_w1T[(size_t)HH * FF];      // w1^T [n=1024][k=4096]
__device__ float g_partial[128];
__device__ float g_D;
__device__ float g_total;

// =================== helpers ===================
__device__ __forceinline__ u32 smem_u32(const void* p) {
    u32 a; asm("{ .reg .u64 t; cvta.to.shared.u64 t, %1; cvt.u32.u64 %0, t; }" : "=r"(a) : "l"(p));
    return a;
}

#define CP16(dst, src) \
    asm volatile("cp.async.cg.shared.global [%0], [%1], 16;" :: "r"(dst), "l"(src) : "memory")
#define CPCOMMIT() asm volatile("cp.async.commit_group;" ::: "memory")
#define CPWAIT1()  asm volatile("cp.async.wait_group 1;" ::: "memory")

#define LDSM4(r, addr) \
    asm volatile("ldmatrix.sync.aligned.m8n8.x4.shared.b16 {%0,%1,%2,%3}, [%4];" \
        : "=r"((r)[0]), "=r"((r)[1]), "=r"((r)[2]), "=r"((r)[3]) : "r"(addr))

// m16n8k16 fp16, fp32 accumulate
#define MMA16(d, a, b0_, b1_) \
    asm volatile("mma.sync.aligned.m16n8k16.row.col.f32.f16.f16.f32 " \
        "{%0,%1,%2,%3}, {%4,%5,%6,%7}, {%8,%9}, {%0,%1,%2,%3};" \
        : "+f"((d)[0]), "+f"((d)[1]), "+f"((d)[2]), "+f"((d)[3]) \
        : "r"((a)[0]), "r"((a)[1]), "r"((a)[2]), "r"((a)[3]), "r"(b0_), "r"(b1_))

// tile: 128 rows x 64 k-halves (128B data), row stride 144B -> conflict-free LDSM/STS
#define TILE_B   18432   /* 128*144 */
#define ROWSTRB  144

// =================== small kernels ===================
__global__ void init_kernel() { g_D = 1.0f; g_total = 0.0f; }

__global__ void conv_x_kernel(const float* __restrict__ x) {
    int i = (blockIdx.x * 256 + threadIdx.x) * 4;
    float4 v = *(const float4*)(x + i);
    __half2 h0 = __floats2half2_rn(v.x, v.y);
    __half2 h1 = __floats2half2_rn(v.z, v.w);
    *(__half2*)(g_xh + i)     = h0;
    *(__half2*)(g_xh + i + 2) = h1;
}

// out[C][R] = half(in[R][C]); block (32,8), grid (C/32, R/32)
__global__ void transpose_w(const float* __restrict__ in, __half* __restrict__ out, int R, int C) {
    __shared__ float t[32][33];
    int c0 = blockIdx.x * 32, r0 = blockIdx.y * 32;
    #pragma unroll
    for (int i = 0; i < 32; i += 8)
        t[threadIdx.y + i][threadIdx.x] = in[(size_t)(r0 + threadIdx.y + i) * C + c0 + threadIdx.x];
    __syncthreads();
    #pragma unroll
    for (int i = 0; i < 32; i += 8)
        out[(size_t)(c0 + threadIdx.y + i) * R + r0 + threadIdx.x] = __float2half_rn(t[threadIdx.x][threadIdx.y + i]);
}

__global__ void reduce_update_kernel(float* __restrict__ outp, int chunk) {
    __shared__ float red[128];
    int t = threadIdx.x;
    red[t] = g_partial[t];
    __syncthreads();
    for (int s = 64; s > 0; s >>= 1) {
        if (t < s) red[t] += red[t + s];
        __syncthreads();
    }
    if (t == 0) {
        float loss = red[0] * (1.0f / (float)(MROWS * HH));
        float tot = g_total + loss;
        g_total = tot;
        g_D = g_D * (1.0f - 0.001f * loss);
        if (chunk == NCHUNK - 1) outp[NOUT] = tot * (1.0f / (float)NCHUNK);
    }
}

// =================== GEMM1: u0/u2 (both weights) + fused SwiGLU -> g_vh ===================
// CTA 128x128, K=1024, k-tile 64. smem stage = [A | B(w0) | B(w2)] = 3*18432; 3 stages.
#define ST1_STAGE (3 * TILE_B)
#define ST1_BYTES (3 * ST1_STAGE)

__device__ __forceinline__ void g1_load(u32 base, int tid, int m0, int n0, int chunk, int kt) {
    #pragma unroll
    for (int i = 0; i < 4; i++) {
        int idx = tid + i * 256;
        int row = idx >> 3, kq = idx & 7;
        int gm = m0 + row;
        int g = ((gm >> 9) << 12) + chunk * CHUNKSZ + (gm & 511);
        const __half* src = g_xh + (size_t)g * HH + kt * 64 + kq * 8;
        CP16(base + (u32)(row * ROWSTRB + kq * 16), src);
    }
    #pragma unroll
    for (int i = 0; i < 8; i++) {
        int idx = tid + i * 256;
        int w = idx >> 10, r2 = idx & 1023;
        int row = r2 >> 3, kq = r2 & 7;
        const __half* src = (w ? g_w2T : g_w0T) + (size_t)(n0 + row) * HH + kt * 64 + kq * 8;
        CP16(base + (u32)(1 + w) * TILE_B + (u32)(row * ROWSTRB + kq * 16), src);
    }
}

__global__ __launch_bounds__(256, 1)
void gemm1_tc(int chunk)
{
    extern __shared__ float smem[];
    const u32 sb = smem_u32(smem);
    const int tid = threadIdx.x, lane = tid & 31, wid = tid >> 5;
    const int wm = wid & 3, wn = wid >> 2;
    const int m0 = blockIdx.y * 128, n0 = blockIdx.x * 128;

    float acc0[2][8][4], acc2[2][8][4];
    #pragma unroll
    for (int a = 0; a < 2; a++)
        #pragma unroll
        for (int b = 0; b < 8; b++)
            #pragma unroll
            for (int c = 0; c < 4; c++) { acc0[a][b][c] = 0.f; acc2[a][b][c] = 0.f; }

    const u32 aoff = (u32)((wm * 32 + (lane & 15)) * ROWSTRB) + ((lane >> 4) & 1) * 16;
    const u32 boff = (u32)((wn * 64 + (lane & 15)) * ROWSTRB) + ((lane >> 4) & 1) * 16;

    g1_load(sb, tid, m0, n0, chunk, 0); CPCOMMIT();
    g1_load(sb + ST1_STAGE, tid, m0, n0, chunk, 1); CPCOMMIT();

    const int KT = HH / 64;  // 16
    for (int kt = 0; kt < KT; ++kt) {
        const u32 base = sb + (u32)(kt % 3) * ST1_STAGE;
        CPWAIT1();
        __syncthreads();
        if (kt + 2 < KT) g1_load(sb + (u32)((kt + 2) % 3) * ST1_STAGE, tid, m0, n0, chunk, kt + 2);
        CPCOMMIT();
        #pragma unroll
        for (int ks = 0; ks < 4; ++ks) {   // 4 x k16
            u32 A[2][4];
            LDSM4(A[0], base + aoff + 0 * 2304 + ks * 32);
            LDSM4(A[1], base + aoff + 1 * 2304 + ks * 32);
            #pragma unroll
            for (int tp = 0; tp < 4; ++tp) {
                u32 b[4], c[4];
                LDSM4(b, base + 1 * TILE_B + boff + tp * 2304 + ks * 32);
                LDSM4(c, base + 2 * TILE_B + boff + tp * 2304 + ks * 32);
                #pragma unroll
                for (int mt = 0; mt < 2; ++mt) {
                    MMA16(acc0[mt][2 * tp],     A[mt], b[0], b[2]);
                    MMA16(acc0[mt][2 * tp + 1], A[mt], b[1], b[3]);
                    MMA16(acc2[mt][2 * tp],     A[mt], c[0], c[2]);
                    MMA16(acc2[mt][2 * tp + 1], A[mt], c[1], c[3]);
                }
            }
        }
    }

    // fused SwiGLU epilogue -> g_vh
    const float D = g_D;
    const int gq = lane >> 2, tg = lane & 3;
    #pragma unroll
    for (int mt = 0; mt < 2; ++mt) {
        #pragma unroll
        for (int nt = 0; nt < 8; ++nt) {
            const int col = n0 + wn * 64 + nt * 8 + tg * 2;
            #pragma unroll
            for (int h = 0; h < 2; ++h) {
                const int row = m0 + wm * 32 + mt * 16 + gq + h * 8;
                float u0a = acc0[mt][nt][h * 2], u0b = acc0[mt][nt][h * 2 + 1];
                float u2a = acc2[mt][nt][h * 2], u2b = acc2[mt][nt][h * 2 + 1];
                float z, s, v0, v1;
                z = D * u0a; s = z / (1.0f + __expf(-z)); v0 = s * u2a;
                z = D * u0b; s = z / (1.0f + __expf(-z)); v1 = s * u2b;
                *(__half2*)&g_vh[(size_t)row * FF + col] = __floats2half2_rn(v0, v1);
            }
        }
    }
}

// =================== GEMM2: out = D^2 * (v @ w1T) + fused loss partials ===================
// CTA 128x128, K=4096, k-tile 64. smem stage = [A | B] = 2*18432; 3 stages.
#define ST2_STAGE (2 * TILE_B)
#define ST2_BYTES (3 * ST2_STAGE)

__device__ __forceinline__ void g2_load(u32 base, int tid, int m0, int n0, int kt) {
    #pragma unroll
    for (int i = 0; i < 4; i++) {
        int idx = tid + i * 256;
        int row = idx >> 3, kq = idx & 7;
        const __half* src = g_vh + (size_t)(m0 + row) * FF + kt * 64 + kq * 8;
        CP16(base + (u32)(row * ROWSTRB + kq * 16), src);
    }
    #pragma unroll
    for (int i = 0; i < 4; i++) {
        int idx = tid + i * 256;
        int row = idx >> 3, kq = idx & 7;
        const __half* src = g_w1T + (size_t)(n0 + row) * FF + kt * 64 + kq * 8;
        CP16(base + TILE_B + (u32)(row * ROWSTRB + kq * 16), src);
    }
}

__global__ __launch_bounds__(256, 1)
void gemm2_tc(const float* __restrict__ x, float* __restrict__ outp, int chunk)
{
    extern __shared__ float smem[];
    const u32 sb = smem_u32(smem);
    const int tid = threadIdx.x, lane = tid & 31, wid = tid >> 5;
    const int wm = wid & 3, wn = wid >> 2;
    const int m0 = blockIdx.y * 128, n0 = blockIdx.x * 128;

    float acc[2][8][4];
    #pragma unroll
    for (int a = 0; a < 2; a++)
        #pragma unroll
        for (int b = 0; b < 8; b++)
            #pragma unroll
            for (int c = 0; c < 4; c++) acc[a][b][c] = 0.f;

    const u32 aoff = (u32)((wm * 32 + (lane & 15)) * ROWSTRB) + ((lane >> 4) & 1) * 16;
    const u32 boff = (u32)((wn * 64 + (lane & 15)) * ROWSTRB) + ((lane >> 4) & 1) * 16;

    g2_load(sb, tid, m0, n0, 0); CPCOMMIT();
    g2_load(sb + ST2_STAGE, tid, m0, n0, 1); CPCOMMIT();

    const int KT = FF / 64;  // 64
    for (int kt = 0; kt < KT; ++kt) {
        const u32 base = sb + (u32)(kt % 3) * ST2_STAGE;
        CPWAIT1();
        __syncthreads();
        if (kt + 2 < KT) g2_load(sb + (u32)((kt + 2) % 3) * ST2_STAGE, tid, m0, n0, kt + 2);
        CPCOMMIT();
        #pragma unroll
        for (int ks = 0; ks < 4; ++ks) {
            u32 A[2][4];
            LDSM4(A[0], base + aoff + 0 * 2304 + ks * 32);
            LDSM4(A[1], base + aoff + 1 * 2304 + ks * 32);
            #pragma unroll
            for (int tp = 0; tp < 4; ++tp) {
                u32 b[4];
                LDSM4(b, base + TILE_B + boff + tp * 2304 + ks * 32);
                #pragma unroll
                for (int mt = 0; mt < 2; ++mt) {
                    MMA16(acc[mt][2 * tp],     A[mt], b[0], b[2]);
                    MMA16(acc[mt][2 * tp + 1], A[mt], b[1], b[3]);
                }
            }
        }
    }

    // epilogue: out = D^2*acc, fused (out - x)^2 partial
    const float D = g_D, D2 = D * D;
    const int gq = lane >> 2, tg = lane & 3;
    float sq = 0.0f;
    #pragma unroll
    for (int mt = 0; mt < 2; ++mt) {
        #pragma unroll
        for (int nt = 0; nt < 8; ++nt) {
            const int col = n0 + wn * 64 + nt * 8 + tg * 2;
            #pragma unroll
            for (int h = 0; h < 2; ++h) {
                const int lm = m0 + wm * 32 + mt * 16 + gq + h * 8;
                const int g = ((lm >> 9) << 12) + chunk * CHUNKSZ + (lm & 511);
                float2 xv = *(const float2*)(x + (size_t)g * HH + col);
                float2 ov;
                ov.x = D2 * acc[mt][nt][h * 2];
                ov.y = D2 * acc[mt][nt][h * 2 + 1];
                *(float2*)(outp + (size_t)g * HH + col) = ov;
                float d0 = ov.x - xv.x, d1 = ov.y - xv.y;
                sq += d0 * d0 + d1 * d1;
            }
        }
    }
    // block reduce
    #pragma unroll
    for (int off = 16; off > 0; off >>= 1)
        sq += __shfl_xor_sync(0xFFFFFFFFu, sq, off);
    __syncthreads();
    float* red = smem;
    if (lane == 0) red[wid] = sq;
    __syncthreads();
    if (tid == 0) {
        float s = 0.f;
        #pragma unroll
        for (int i = 0; i < 8; i++) s += red[i];
        g_partial[blockIdx.y * 8 + blockIdx.x] = s;
    }
}

// =================== host ===================
extern "C" void kernel_launch(void* const* d_in, const int* in_sizes, int n_in,
                              void* d_out, int out_size)
{
    const float* x  = (const float*)d_in[0];
    const float* w0 = (const float*)d_in[1];
    const float* w1 = (const float*)d_in[2];
    const float* w2 = (const float*)d_in[3];
    float* out = (float*)d_out;

    cudaFuncSetAttribute(gemm1_tc, cudaFuncAttributeMaxDynamicSharedMemorySize, ST1_BYTES);
    cudaFuncSetAttribute(gemm2_tc, cudaFuncAttributeMaxDynamicSharedMemorySize, ST2_BYTES);

    __half *p0, *p1, *p2;
    cudaGetSymbolAddress((void**)&p0, g_w0T);
    cudaGetSymbolAddress((void**)&p1, g_w1T);
    cudaGetSymbolAddress((void**)&p2, g_w2T);

    init_kernel<<<1, 1>>>();
    conv_x_kernel<<<NOUT / 1024, 256>>>(x);
    transpose_w<<<dim3(FF / 32, HH / 32), dim3(32, 8)>>>(w0, p0, HH, FF);
    transpose_w<<<dim3(FF / 32, HH / 32), dim3(32, 8)>>>(w2, p2, HH, FF);
    transpose_w<<<dim3(HH / 32, FF / 32), dim3(32, 8)>>>(w1, p1, FF, HH);

    for (int c = 0; c < NCHUNK; ++c) {
        gemm1_tc<<<dim3(32, 16), 256, ST1_BYTES>>>(c);
        gemm2_tc<<<dim3(8, 16), 256, ST2_BYTES>>>(x, out, c);
        reduce_update_kernel<<<1, 128>>>(out, c);
    }
}

// round 7
// speedup vs baseline: 5.5667x; 1.0685x over previous
#include <cuda_runtime.h>
#include <cuda_fp16.h>
#include <cstdint>

typedef uint32_t u32;

#define CHUNKSZ 512
#define NCHUNK  8
#define HH      1024
#define FF      4096
#define MROWS   2048
#define NOUT    16777216

// ---- scratch (device globals; no allocations allowed) ----
__device__ __half g_xh[(size_t)NOUT];          // fp16 x (32MB)
__device__ __half g_vh[(size_t)MROWS * FF];    // v = silu(D*u0)*u2 (16MB)
__device__ __half g_w0T[(size_t)FF * HH];      // w0^T [n=4096][k=1024]
__device__ __half g_w2T[(size_t)FF * HH];
__device__ __half g_w1T[(size_t)HH * FF];      // w1^T [n=1024][k=4096]
__device__ float g_partial[128];
__device__ float g_D;
__device__ float g_total;

// =================== helpers ===================
__device__ __forceinline__ u32 smem_u32(const void* p) {
    u32 a; asm("{ .reg .u64 t; cvta.to.shared.u64 t, %1; cvt.u32.u64 %0, t; }" : "=r"(a) : "l"(p));
    return a;
}

#define CP16(dst, src) \
    asm volatile("cp.async.cg.shared.global [%0], [%1], 16;" :: "r"(dst), "l"(src) : "memory")
#define CPCOMMIT() asm volatile("cp.async.commit_group;" ::: "memory")
#define CPWAIT1()  asm volatile("cp.async.wait_group 1;" ::: "memory")

#define LDSM4(r, addr) \
    asm volatile("ldmatrix.sync.aligned.m8n8.x4.shared.b16 {%0,%1,%2,%3}, [%4];" \
        : "=r"((r)[0]), "=r"((r)[1]), "=r"((r)[2]), "=r"((r)[3]) : "r"(addr))

// m16n8k16 fp16, fp32 accumulate
#define MMA16(d, a, b0_, b1_) \
    asm volatile("mma.sync.aligned.m16n8k16.row.col.f32.f16.f16.f32 " \
        "{%0,%1,%2,%3}, {%4,%5,%6,%7}, {%8,%9}, {%0,%1,%2,%3};" \
        : "+f"((d)[0]), "+f"((d)[1]), "+f"((d)[2]), "+f"((d)[3]) \
        : "r"((a)[0]), "r"((a)[1]), "r"((a)[2]), "r"((a)[3]), "r"(b0_), "r"(b1_))

// tile: 128 rows x 64 k-halves (128B data), row stride 144B -> conflict-free LDSM/STS
#define TILE_B   18432   /* 128*144 */
#define ROWSTRB  144

// =================== small kernels ===================
__global__ void init_kernel() { g_D = 1.0f; g_total = 0.0f; }

__global__ void conv_x_kernel(const float* __restrict__ x) {
    int i = (blockIdx.x * 256 + threadIdx.x) * 4;
    float4 v = *(const float4*)(x + i);
    __half2 h0 = __floats2half2_rn(v.x, v.y);
    __half2 h1 = __floats2half2_rn(v.z, v.w);
    *(__half2*)(g_xh + i)     = h0;
    *(__half2*)(g_xh + i + 2) = h1;
}

// out[C][R] = half(in[R][C]); block (32,8), grid (C/32, R/32)
__global__ void transpose_w(const float* __restrict__ in, __half* __restrict__ out, int R, int C) {
    __shared__ float t[32][33];
    int c0 = blockIdx.x * 32, r0 = blockIdx.y * 32;
    #pragma unroll
    for (int i = 0; i < 32; i += 8)
        t[threadIdx.y + i][threadIdx.x] = in[(size_t)(r0 + threadIdx.y + i) * C + c0 + threadIdx.x];
    __syncthreads();
    #pragma unroll
    for (int i = 0; i < 32; i += 8)
        out[(size_t)(c0 + threadIdx.y + i) * R + r0 + threadIdx.x] = __float2half_rn(t[threadIdx.x][threadIdx.y + i]);
}

__global__ void reduce_update_kernel(float* __restrict__ outp, int chunk) {
    __shared__ float red[128];
    int t = threadIdx.x;
    red[t] = g_partial[t];
    __syncthreads();
    for (int s = 64; s > 0; s >>= 1) {
        if (t < s) red[t] += red[t + s];
        __syncthreads();
    }
    if (t == 0) {
        float loss = red[0] * (1.0f / (float)(MROWS * HH));
        float tot = g_total + loss;
        g_total = tot;
        g_D = g_D * (1.0f - 0.001f * loss);
        if (chunk == NCHUNK - 1) outp[NOUT] = tot * (1.0f / (float)NCHUNK);
    }
}

// =================== GEMM1: u0/u2 (both weights) + fused SwiGLU -> g_vh ===================
// CTA 128x128, 512 threads (4x4 warps, warp tile 32x32), K=1024, k-tile 64.
// smem stage = [A | B(w0) | B(w2)] = 3*18432; 3 stages = 165888 B.
#define ST1_STAGE (3 * TILE_B)
#define ST1_BYTES (3 * ST1_STAGE)

__device__ __forceinline__ void g1_load(u32 base, int tid, int m0, int n0, int chunk, int kt) {
    #pragma unroll
    for (int i = 0; i < 2; i++) {
        int idx = tid + i * 512;
        int row = idx >> 3, kq = idx & 7;
        int gm = m0 + row;
        int g = ((gm >> 9) << 12) + chunk * CHUNKSZ + (gm & 511);
        const __half* src = g_xh + (size_t)g * HH + kt * 64 + kq * 8;
        CP16(base + (u32)(row * ROWSTRB + kq * 16), src);
    }
    #pragma unroll
    for (int i = 0; i < 4; i++) {
        int idx = tid + i * 512;
        int w = idx >> 10, r2 = idx & 1023;
        int row = r2 >> 3, kq = r2 & 7;
        const __half* src = (w ? g_w2T : g_w0T) + (size_t)(n0 + row) * HH + kt * 64 + kq * 8;
        CP16(base + (u32)(1 + w) * TILE_B + (u32)(row * ROWSTRB + kq * 16), src);
    }
}

__global__ __launch_bounds__(512, 1)
void gemm1_tc(int chunk)
{
    extern __shared__ float smem[];
    const u32 sb = smem_u32(smem);
    const int tid = threadIdx.x, lane = tid & 31, wid = tid >> 5;
    const int wm = wid & 3, wn = wid >> 2;            // 4x4 warp grid
    const int m0 = blockIdx.y * 128, n0 = blockIdx.x * 128;

    float acc0[2][4][4], acc2[2][4][4];
    #pragma unroll
    for (int a = 0; a < 2; a++)
        #pragma unroll
        for (int b = 0; b < 4; b++)
            #pragma unroll
            for (int c = 0; c < 4; c++) { acc0[a][b][c] = 0.f; acc2[a][b][c] = 0.f; }

    const u32 aoff = (u32)((wm * 32 + (lane & 15)) * ROWSTRB) + ((lane >> 4) & 1) * 16;
    const u32 boff = (u32)((wn * 32 + (lane & 15)) * ROWSTRB) + ((lane >> 4) & 1) * 16;

    g1_load(sb, tid, m0, n0, chunk, 0); CPCOMMIT();
    g1_load(sb + ST1_STAGE, tid, m0, n0, chunk, 1); CPCOMMIT();

    const int KT = HH / 64;  // 16
    for (int kt = 0; kt < KT; ++kt) {
        const u32 base = sb + (u32)(kt % 3) * ST1_STAGE;
        CPWAIT1();
        __syncthreads();
        if (kt + 2 < KT) g1_load(sb + (u32)((kt + 2) % 3) * ST1_STAGE, tid, m0, n0, chunk, kt + 2);
        CPCOMMIT();
        #pragma unroll
        for (int ks = 0; ks < 4; ++ks) {   // 4 x k16
            u32 A[2][4];
            LDSM4(A[0], base + aoff + 0 * 2304 + ks * 32);
            LDSM4(A[1], base + aoff + 1 * 2304 + ks * 32);
            #pragma unroll
            for (int tp = 0; tp < 2; ++tp) {   // 2 x (2 n8-tiles)
                u32 b[4], c[4];
                LDSM4(b, base + 1 * TILE_B + boff + tp * 2304 + ks * 32);
                LDSM4(c, base + 2 * TILE_B + boff + tp * 2304 + ks * 32);
                #pragma unroll
                for (int mt = 0; mt < 2; ++mt) {
                    MMA16(acc0[mt][2 * tp],     A[mt], b[0], b[2]);
                    MMA16(acc0[mt][2 * tp + 1], A[mt], b[1], b[3]);
                    MMA16(acc2[mt][2 * tp],     A[mt], c[0], c[2]);
                    MMA16(acc2[mt][2 * tp + 1], A[mt], c[1], c[3]);
                }
            }
        }
    }

    // fused SwiGLU epilogue -> g_vh
    const float D = g_D;
    const int gq = lane >> 2, tg = lane & 3;
    #pragma unroll
    for (int mt = 0; mt < 2; ++mt) {
        #pragma unroll
        for (int nt = 0; nt < 4; ++nt) {
            const int col = n0 + wn * 32 + nt * 8 + tg * 2;
            #pragma unroll
            for (int h = 0; h < 2; ++h) {
                const int row = m0 + wm * 32 + mt * 16 + gq + h * 8;
                float u0a = acc0[mt][nt][h * 2], u0b = acc0[mt][nt][h * 2 + 1];
                float u2a = acc2[mt][nt][h * 2], u2b = acc2[mt][nt][h * 2 + 1];
                float z, s, v0, v1;
                z = D * u0a; s = z / (1.0f + __expf(-z)); v0 = s * u2a;
                z = D * u0b; s = z / (1.0f + __expf(-z)); v1 = s * u2b;
                *(__half2*)&g_vh[(size_t)row * FF + col] = __floats2half2_rn(v0, v1);
            }
        }
    }
}

// =================== GEMM2: out = D^2 * (v @ w1T) + fused loss partials ===================
// CTA 128x128, 512 threads (4x4 warps, warp tile 32x32), K=4096, k-tile 64.
// smem stage = [A | B] = 2*18432; 3 stages = 110592 B.
#define ST2_STAGE (2 * TILE_B)
#define ST2_BYTES (3 * ST2_STAGE)

__device__ __forceinline__ void g2_load(u32 base, int tid, int m0, int n0, int kt) {
    #pragma unroll
    for (int i = 0; i < 2; i++) {
        int idx = tid + i * 512;
        int row = idx >> 3, kq = idx & 7;
        const __half* src = g_vh + (size_t)(m0 + row) * FF + kt * 64 + kq * 8;
        CP16(base + (u32)(row * ROWSTRB + kq * 16), src);
    }
    #pragma unroll
    for (int i = 0; i < 2; i++) {
        int idx = tid + i * 512;
        int row = idx >> 3, kq = idx & 7;
        const __half* src = g_w1T + (size_t)(n0 + row) * FF + kt * 64 + kq * 8;
        CP16(base + TILE_B + (u32)(row * ROWSTRB + kq * 16), src);
    }
}

__global__ __launch_bounds__(512, 1)
void gemm2_tc(const float* __restrict__ x, float* __restrict__ outp, int chunk)
{
    extern __shared__ float smem[];
    const u32 sb = smem_u32(smem);
    const int tid = threadIdx.x, lane = tid & 31, wid = tid >> 5;
    const int wm = wid & 3, wn = wid >> 2;
    const int m0 = blockIdx.y * 128, n0 = blockIdx.x * 128;

    float acc[2][4][4];
    #pragma unroll
    for (int a = 0; a < 2; a++)
        #pragma unroll
        for (int b = 0; b < 4; b++)
            #pragma unroll
            for (int c = 0; c < 4; c++) acc[a][b][c] = 0.f;

    const u32 aoff = (u32)((wm * 32 + (lane & 15)) * ROWSTRB) + ((lane >> 4) & 1) * 16;
    const u32 boff = (u32)((wn * 32 + (lane & 15)) * ROWSTRB) + ((lane >> 4) & 1) * 16;

    g2_load(sb, tid, m0, n0, 0); CPCOMMIT();
    g2_load(sb + ST2_STAGE, tid, m0, n0, 1); CPCOMMIT();

    const int KT = FF / 64;  // 64
    for (int kt = 0; kt < KT; ++kt) {
        const u32 base = sb + (u32)(kt % 3) * ST2_STAGE;
        CPWAIT1();
        __syncthreads();
        if (kt + 2 < KT) g2_load(sb + (u32)((kt + 2) % 3) * ST2_STAGE, tid, m0, n0, kt + 2);
        CPCOMMIT();
        #pragma unroll
        for (int ks = 0; ks < 4; ++ks) {
            u32 A[2][4];
            LDSM4(A[0], base + aoff + 0 * 2304 + ks * 32);
            LDSM4(A[1], base + aoff + 1 * 2304 + ks * 32);
            #pragma unroll
            for (int tp = 0; tp < 2; ++tp) {
                u32 b[4];
                LDSM4(b, base + TILE_B + boff + tp * 2304 + ks * 32);
                #pragma unroll
                for (int mt = 0; mt < 2; ++mt) {
                    MMA16(acc[mt][2 * tp],     A[mt], b[0], b[2]);
                    MMA16(acc[mt][2 * tp + 1], A[mt], b[1], b[3]);
                }
            }
        }
    }

    // epilogue: out = D^2*acc, fused (out - x)^2 partial
    const float D = g_D, D2 = D * D;
    const int gq = lane >> 2, tg = lane & 3;
    float sq = 0.0f;
    #pragma unroll
    for (int mt = 0; mt < 2; ++mt) {
        #pragma unroll
        for (int nt = 0; nt < 4; ++nt) {
            const int col = n0 + wn * 32 + nt * 8 + tg * 2;
            #pragma unroll
            for (int h = 0; h < 2; ++h) {
                const int lm = m0 + wm * 32 + mt * 16 + gq + h * 8;
                const int g = ((lm >> 9) << 12) + chunk * CHUNKSZ + (lm & 511);
                float2 xv = *(const float2*)(x + (size_t)g * HH + col);
                float2 ov;
                ov.x = D2 * acc[mt][nt][h * 2];
                ov.y = D2 * acc[mt][nt][h * 2 + 1];
                *(float2*)(outp + (size_t)g * HH + col) = ov;
                float d0 = ov.x - xv.x, d1 = ov.y - xv.y;
                sq += d0 * d0 + d1 * d1;
            }
        }
    }
    // block reduce (16 warps)
    #pragma unroll
    for (int off = 16; off > 0; off >>= 1)
        sq += __shfl_xor_sync(0xFFFFFFFFu, sq, off);
    __syncthreads();
    float* red = smem;
    if (lane == 0) red[wid] = sq;
    __syncthreads();
    if (tid == 0) {
        float s = 0.f;
        #pragma unroll
        for (int i = 0; i < 16; i++) s += red[i];
        g_partial[blockIdx.y * 8 + blockIdx.x] = s;
    }
}

// =================== host ===================
extern "C" void kernel_launch(void* const* d_in, const int* in_sizes, int n_in,
                              void* d_out, int out_size)
{
    const float* x  = (const float*)d_in[0];
    const float* w0 = (const float*)d_in[1];
    const float* w1 = (const float*)d_in[2];
    const float* w2 = (const float*)d_in[3];
    float* out = (float*)d_out;

    cudaFuncSetAttribute(gemm1_tc, cudaFuncAttributeMaxDynamicSharedMemorySize, ST1_BYTES);
    cudaFuncSetAttribute(gemm2_tc, cudaFuncAttributeMaxDynamicSharedMemorySize, ST2_BYTES);

    __half *p0, *p1, *p2;
    cudaGetSymbolAddress((void**)&p0, g_w0T);
    cudaGetSymbolAddress((void**)&p1, g_w1T);
    cudaGetSymbolAddress((void**)&p2, g_w2T);

    init_kernel<<<1, 1>>>();
    conv_x_kernel<<<NOUT / 1024, 256>>>(x);
    transpose_w<<<dim3(FF / 32, HH / 32), dim3(32, 8)>>>(w0, p0, HH, FF);
    transpose_w<<<dim3(FF / 32, HH / 32), dim3(32, 8)>>>(w2, p2, HH, FF);
    transpose_w<<<dim3(HH / 32, FF / 32), dim3(32, 8)>>>(w1, p1, FF, HH);

    for (int c = 0; c < NCHUNK; ++c) {
        gemm1_tc<<<dim3(32, 16), 512, ST1_BYTES>>>(c);
        gemm2_tc<<<dim3(8, 16), 512, ST2_BYTES>>>(x, out, c);
        reduce_update_kernel<<<1, 128>>>(out, c);
    }
}